// round 12
// baseline (speedup 1.0000x reference)
#include <cuda_runtime.h>
#include <cuda_bf16.h>
#include <cstdint>
#include <math.h>

// ===========================================================================
// Actor_15324443312913 — HMMA bf16 hi/lo-split grouped GEMM, round 12.
//  * BIG kernel reworked: 128 thr, 2x2 warps, warp tile 64x64
//    -> 6 MMA per ldmatrix (was 4), smem dup (2x,2x) (was 4x,2x),
//       LSU no longer co-limiting; tensor-bound by model.
//  * N-guards dropped in BIG kernel (all big layers have N % 128 == 0).
// ===========================================================================

#define BATCH 4096
#define LDE   (85 * 128)

typedef __nv_bfloat16 bf16;

#define WT_TOTAL 16617472
__device__ bf16 g_whi[WT_TOTAL];
__device__ bf16 g_wlo[WT_TOTAL];
__device__ bf16 g_h1h[33554432], g_h1l[33554432];
__device__ bf16 g_h2h[33554432], g_h2l[33554432];
__device__ bf16 g_th[44564480], g_tl[44564480];
__device__ bf16 g_sh[1048576], g_sl[1048576];

// ---------------- helpers ---------------------------------------------------
__device__ __forceinline__ uint32_t smem_u32(const void* p) {
    uint32_t a;
    asm("{ .reg .u64 t; cvta.to.shared.u64 t, %1; cvt.u32.u64 %0, t; }"
        : "=r"(a) : "l"(p));
    return a;
}
__device__ __forceinline__ void ldsm4(uint32_t* r, uint32_t addr) {
    asm volatile("ldmatrix.sync.aligned.m8n8.x4.shared.b16 {%0,%1,%2,%3}, [%4];"
                 : "=r"(r[0]), "=r"(r[1]), "=r"(r[2]), "=r"(r[3]) : "r"(addr));
}
__device__ __forceinline__ void mma_bf16(float* c, const uint32_t* a,
                                         const uint32_t* b) {
    asm volatile(
        "mma.sync.aligned.m16n8k16.row.col.f32.bf16.bf16.f32 "
        "{%0,%1,%2,%3},{%4,%5,%6,%7},{%8,%9},{%0,%1,%2,%3};"
        : "+f"(c[0]), "+f"(c[1]), "+f"(c[2]), "+f"(c[3])
        : "r"(a[0]), "r"(a[1]), "r"(a[2]), "r"(a[3]), "r"(b[0]), "r"(b[1]));
}
__device__ __forceinline__ void cpa16(uint32_t dst, const void* src, bool p) {
    int sz = p ? 16 : 0;
    asm volatile("cp.async.cg.shared.global [%0], [%1], 16, %2;"
                 :: "r"(dst), "l"(src), "r"(sz));
}
#define CP_COMMIT() asm volatile("cp.async.commit_group;" ::: "memory")
#define CP_WAIT0()  asm volatile("cp.async.wait_group 0;" ::: "memory")

__device__ __forceinline__ void split2(float x, float y, uint32_t& h2,
                                       uint32_t& l2) {
    __nv_bfloat162 h, l;
    h.x = __float2bfloat16(x); h.y = __float2bfloat16(y);
    l.x = __float2bfloat16(x - __bfloat162float(h.x));
    l.y = __float2bfloat16(y - __bfloat162float(h.y));
    h2 = *(uint32_t*)&h;
    l2 = *(uint32_t*)&l;
}

// ---------------- fused weight prep ----------------------------------------
struct PrepJobs {
    const float* src[15];
    int dstOff[15];
    int K[15], N[15];
    int tileBase[16];
};

__global__ void prep_all(PrepJobs J, bf16* __restrict__ hi,
                         bf16* __restrict__ lo) {
    __shared__ float t[32][33];
    const int bz = blockIdx.x;
    int j = 0;
#pragma unroll
    for (int i = 1; i < 15; i++)
        if (bz >= J.tileBase[i]) j = i;
    const int rem = bz - J.tileBase[j];
    const int K = J.K[j], N = J.N[j];
    const int ntx = N >> 5;
    const int perG = ntx * (K >> 5);
    const int g = rem / perG;
    const int tt = rem % perG;
    const int k0 = (tt / ntx) << 5, n0 = (tt % ntx) << 5;

    const long grp = (long)K * N;
    const float* ing = J.src[j] + (long)g * grp;
    bf16* hig = hi + J.dstOff[j] + (long)g * grp;
    bf16* log_ = lo + J.dstOff[j] + (long)g * grp;
    const int tx = threadIdx.x, ty = threadIdx.y;
#pragma unroll
    for (int i = 0; i < 32; i += 8)
        t[ty + i][tx] = ing[(long)(k0 + ty + i) * N + n0 + tx];
    __syncthreads();
#pragma unroll
    for (int i = 0; i < 32; i += 8) {
        float v = t[tx][ty + i];
        bf16 h = __float2bfloat16(v);
        float r = v - __bfloat162float(h);
        long o = (long)(n0 + ty + i) * K + k0 + tx;
        hig[o] = h;
        log_[o] = __float2bfloat16(r);
    }
}

__global__ void cvt_split(const float* __restrict__ in, bf16* __restrict__ hi,
                          bf16* __restrict__ lo, int n4) {
    int i = blockIdx.x * blockDim.x + threadIdx.x;
    if (i < n4) {
        float4 t = ((const float4*)in)[i];
        uint32_t h01, l01, h23, l23;
        split2(t.x, t.y, h01, l01);
        split2(t.z, t.w, h23, l23);
        ((uint2*)hi)[i] = make_uint2(h01, h23);
        ((uint2*)lo)[i] = make_uint2(l01, l23);
    }
}

// ---------------- epilogue helper -------------------------------------------
template <int ACT, bool WF32, bool WB16>
__device__ __forceinline__ void epi_store(const float* c, const float* sBias,
                                          int lc, int r0, float* Cfg, int ldcf,
                                          bf16* OHg, bf16* OLg, int ldo,
                                          int col) {
    float b0 = sBias[lc], b1 = sBias[lc + 1];
    float2 v0 = make_float2(c[0] + b0, c[1] + b1);
    float2 v1 = make_float2(c[2] + b0, c[3] + b1);
    if (ACT == 1) {
        v0.x = fmaxf(v0.x, 0.f); v0.y = fmaxf(v0.y, 0.f);
        v1.x = fmaxf(v1.x, 0.f); v1.y = fmaxf(v1.y, 0.f);
    }
    if (ACT == 2) {
        v0.x = tanhf(v0.x); v0.y = tanhf(v0.y);
        v1.x = tanhf(v1.x); v1.y = tanhf(v1.y);
    }
    if (WF32) {
        *(float2*)(Cfg + (long)r0 * ldcf + col) = v0;
        *(float2*)(Cfg + (long)(r0 + 8) * ldcf + col) = v1;
    }
    if (WB16) {
        uint32_t h2, l2;
        split2(v0.x, v0.y, h2, l2);
        *(uint32_t*)(OHg + (long)r0 * ldo + col) = h2;
        *(uint32_t*)(OLg + (long)r0 * ldo + col) = l2;
        split2(v1.x, v1.y, h2, l2);
        *(uint32_t*)(OHg + (long)(r0 + 8) * ldo + col) = h2;
        *(uint32_t*)(OLg + (long)(r0 + 8) * ldo + col) = l2;
    }
}

// ---------------- BIG GEMM: 128x128 tile, 128 thr, warp tile 64x64 ----------
#define STAGE_BYTES 40960
#define SMEM_BYTES  (2 * STAGE_BYTES + 512)

__device__ __forceinline__ void stage_tiles3(
    uint32_t sb, const bf16* Ahg, const bf16* Alg, int lda, const bf16* WHg,
    const bf16* WLg, int K, int k0, int tid) {
#pragma unroll
    for (int i = 0; i < 4; i++) {
        int v = tid + (i << 7);          // 0..511
        int r = v >> 2, q = v & 3;       // row 0..127, 16B-col 0..3
        uint32_t d = (uint32_t)(r * 80 + (q << 4));
        long ao = (long)r * lda + k0 + (q << 3);
        cpa16(sb + d, Ahg + ao, true);
        cpa16(sb + 10240 + d, Alg + ao, true);
        long bo = (long)r * K + k0 + (q << 3);
        cpa16(sb + 20480 + d, WHg + bo, true);
        cpa16(sb + 30720 + d, WLg + bo, true);
    }
}

template <int ACT, bool WF32, bool WB16>
__global__ __launch_bounds__(128)
void gemm3(const bf16* __restrict__ Ah, const bf16* __restrict__ Al, long aGrp,
           int lda, const bf16* __restrict__ WH, const bf16* __restrict__ WL,
           long wGrp, const float* __restrict__ Bias, long bGrp,
           float* __restrict__ Cf, long cfGrp, int ldcf,
           bf16* __restrict__ OH, bf16* __restrict__ OL, long oGrp, int ldo,
           int N, int K) {
    extern __shared__ char smem[];
    const uint32_t sbs = smem_u32(smem);
    float* sBias = (float*)(smem + 2 * STAGE_BYTES);

    const int tid = threadIdx.x, w = tid >> 5, L = tid & 31;
    const int wr = w >> 1, wc = w & 1;   // 2x2 warp grid, warp tile 64x64
    const int g = blockIdx.z;
    const int m0 = blockIdx.y * 128, n0 = blockIdx.x * 128;

    const bf16* Ahg = Ah + (long)g * aGrp + (long)m0 * lda;
    const bf16* Alg = Al + (long)g * aGrp + (long)m0 * lda;
    const bf16* WHg = WH + (long)g * wGrp + (long)n0 * K;
    const bf16* WLg = WL + (long)g * wGrp + (long)n0 * K;

    sBias[tid] = Bias[(long)g * bGrp + n0 + tid];

    float acc[128];
#pragma unroll
    for (int i = 0; i < 128; i++) acc[i] = 0.f;

    const uint32_t a_off =
        (uint32_t)((wr * 64 + (L & 7) + ((L >> 3) & 1) * 8) * 80 +
                   ((L >> 4) & 1) * 16);
    const uint32_t b_off =
        (uint32_t)((wc * 64 + (L & 7) + ((L >> 4) & 1) * 8) * 80 +
                   ((L >> 3) & 1) * 16);

    const int nch = K >> 5;
    stage_tiles3(sbs, Ahg, Alg, lda, WHg, WLg, K, 0, tid);
    CP_COMMIT();

    for (int ch = 0; ch < nch; ch++) {
        CP_WAIT0();
        __syncthreads();
        if (ch + 1 < nch)
            stage_tiles3(sbs + ((ch + 1) & 1) * STAGE_BYTES, Ahg, Alg, lda,
                         WHg, WLg, K, (ch + 1) << 5, tid);
        CP_COMMIT();

        const uint32_t ab = sbs + (ch & 1) * STAGE_BYTES;
        const uint32_t bb = ab + 20480;
#pragma unroll
        for (int s = 0; s < 2; s++) {
            uint32_t ah[16], al[16], bh[16], bl[16];
#pragma unroll
            for (int p = 0; p < 4; p++) {
                uint32_t bd = b_off + p * 1280 + s * 32;
                ldsm4(&bh[p * 4], bb + bd);
                ldsm4(&bl[p * 4], bb + 10240 + bd);
            }
#pragma unroll
            for (int mt = 0; mt < 4; mt++) {
                uint32_t ad = a_off + mt * 1280 + s * 32;
                ldsm4(&ah[mt * 4], ab + ad);
                ldsm4(&al[mt * 4], ab + 10240 + ad);
            }
            // 32 independent acc tiles per term group
#pragma unroll
            for (int mt = 0; mt < 4; mt++)
#pragma unroll
                for (int nt = 0; nt < 8; nt++)
                    mma_bf16(&acc[(mt * 8 + nt) * 4], &ah[mt * 4],
                             &bh[nt * 2]);  // hi*hi
#pragma unroll
            for (int mt = 0; mt < 4; mt++)
#pragma unroll
                for (int nt = 0; nt < 8; nt++)
                    mma_bf16(&acc[(mt * 8 + nt) * 4], &ah[mt * 4],
                             &bl[nt * 2]);  // hi*lo
#pragma unroll
            for (int mt = 0; mt < 4; mt++)
#pragma unroll
                for (int nt = 0; nt < 8; nt++)
                    mma_bf16(&acc[(mt * 8 + nt) * 4], &al[mt * 4],
                             &bh[nt * 2]);  // lo*hi
        }
    }

    const int quad = L >> 2, ql = L & 3;
    float* Cfg = Cf + (long)g * cfGrp;
    bf16* OHg = OH + (long)g * oGrp;
    bf16* OLg = OL + (long)g * oGrp;
#pragma unroll
    for (int mt = 0; mt < 4; mt++) {
        int r0 = m0 + wr * 64 + mt * 16 + quad;
#pragma unroll
        for (int nt = 0; nt < 8; nt++) {
            int lc = wc * 64 + nt * 8 + (ql << 1);
            epi_store<ACT, WF32, WB16>(&acc[(mt * 8 + nt) * 4], sBias, lc, r0,
                                       Cfg, ldcf, OHg, OLg, ldo, n0 + lc);
        }
    }
}

// ---------------- SMALL GEMM: 64x64 tile, 128 thr ---------------------------
#define SSTAGE 20480
#define SSMEM  (2 * SSTAGE + 512)

__device__ __forceinline__ void stage_small(
    uint32_t sb, const bf16* Ahg, const bf16* Alg, int lda, const bf16* WHg,
    const bf16* WLg, int K, int k0, int n0, int N, int tid) {
#pragma unroll
    for (int i = 0; i < 2; i++) {
        int v = tid + (i << 7);
        int r = v >> 2, q = v & 3;
        uint32_t d = (uint32_t)(r * 80 + (q << 4));
        long ao = (long)r * lda + k0 + (q << 3);
        cpa16(sb + d, Ahg + ao, true);
        cpa16(sb + 5120 + d, Alg + ao, true);
        bool bp = (n0 + r) < N;
        long bo = bp ? ((long)r * K + k0 + (q << 3)) : 0;
        cpa16(sb + 10240 + d, WHg + bo, bp);
        cpa16(sb + 15360 + d, WLg + bo, bp);
    }
}

template <int ACT, bool WF32, bool WB16>
__global__ __launch_bounds__(128, 4)
void gemm_s(const bf16* __restrict__ Ah, const bf16* __restrict__ Al,
            long aGrp, int lda, const bf16* __restrict__ WH,
            const bf16* __restrict__ WL, long wGrp,
            const float* __restrict__ Bias, long bGrp,
            float* __restrict__ Cf, long cfGrp, int ldcf,
            bf16* __restrict__ OH, bf16* __restrict__ OL, long oGrp, int ldo,
            int N, int K) {
    extern __shared__ char smem[];
    const uint32_t sbs = smem_u32(smem);
    float* sBias = (float*)(smem + 2 * SSTAGE);

    const int tid = threadIdx.x, w = tid >> 5, L = tid & 31;
    const int wr = w >> 1, wc = w & 1;
    const int g = blockIdx.z;
    const int m0 = blockIdx.y * 64, n0 = blockIdx.x * 64;

    const bf16* Ahg = Ah + (long)g * aGrp + (long)m0 * lda;
    const bf16* Alg = Al + (long)g * aGrp + (long)m0 * lda;
    const bf16* WHg = WH + (long)g * wGrp + (long)n0 * K;
    const bf16* WLg = WL + (long)g * wGrp + (long)n0 * K;

    if (tid < 64) {
        int c = n0 + tid;
        sBias[tid] = (c < N) ? Bias[(long)g * bGrp + c] : 0.f;
    }

    float acc[32];
#pragma unroll
    for (int i = 0; i < 32; i++) acc[i] = 0.f;

    const uint32_t a_off =
        (uint32_t)((wr * 32 + (L & 7) + ((L >> 3) & 1) * 8) * 80 +
                   ((L >> 4) & 1) * 16);
    const uint32_t b_off =
        (uint32_t)((wc * 32 + (L & 7) + ((L >> 4) & 1) * 8) * 80 +
                   ((L >> 3) & 1) * 16);

    const int nch = K >> 5;
    stage_small(sbs, Ahg, Alg, lda, WHg, WLg, K, 0, n0, N, tid);
    CP_COMMIT();

    for (int ch = 0; ch < nch; ch++) {
        CP_WAIT0();
        __syncthreads();
        if (ch + 1 < nch)
            stage_small(sbs + ((ch + 1) & 1) * SSTAGE, Ahg, Alg, lda, WHg, WLg,
                        K, (ch + 1) << 5, n0, N, tid);
        CP_COMMIT();

        const uint32_t ab = sbs + (ch & 1) * SSTAGE;
        const uint32_t bb = ab + 10240;
#pragma unroll
        for (int s = 0; s < 2; s++) {
            uint32_t ah[8], al[8], bh[8], bl[8];
#pragma unroll
            for (int p = 0; p < 2; p++) {
                uint32_t bd = b_off + p * 1280 + s * 32;
                ldsm4(&bh[p * 4], bb + bd);
                ldsm4(&bl[p * 4], bb + 5120 + bd);
            }
#pragma unroll
            for (int mt = 0; mt < 2; mt++) {
                uint32_t ad = a_off + mt * 1280 + s * 32;
                ldsm4(&ah[mt * 4], ab + ad);
                ldsm4(&al[mt * 4], ab + 5120 + ad);
            }
#pragma unroll
            for (int p = 0; p < 2; p++) {
#pragma unroll
                for (int mt = 0; mt < 2; mt++)
#pragma unroll
                    for (int t = 0; t < 2; t++)
                        mma_bf16(&acc[(mt * 4 + p * 2 + t) * 4], &ah[mt * 4],
                                 &bh[p * 4 + t * 2]);
#pragma unroll
                for (int mt = 0; mt < 2; mt++)
#pragma unroll
                    for (int t = 0; t < 2; t++)
                        mma_bf16(&acc[(mt * 4 + p * 2 + t) * 4], &ah[mt * 4],
                                 &bl[p * 4 + t * 2]);
#pragma unroll
                for (int mt = 0; mt < 2; mt++)
#pragma unroll
                    for (int t = 0; t < 2; t++)
                        mma_bf16(&acc[(mt * 4 + p * 2 + t) * 4], &al[mt * 4],
                                 &bh[p * 4 + t * 2]);
            }
        }
    }

    const int quad = L >> 2, ql = L & 3;
    float* Cfg = Cf + (long)g * cfGrp;
    bf16* OHg = OH + (long)g * oGrp;
    bf16* OLg = OL + (long)g * oGrp;
#pragma unroll
    for (int mt = 0; mt < 2; mt++) {
        int r0 = m0 + wr * 32 + mt * 16 + quad;
#pragma unroll
        for (int nt = 0; nt < 4; nt++) {
            int lc = wc * 32 + nt * 8 + (ql << 1);
            int col = n0 + lc;
            if (col < N)
                epi_store<ACT, WF32, WB16>(&acc[(mt * 4 + nt) * 4], sBias, lc,
                                           r0, Cfg, ldcf, OHg, OLg, ldo, col);
        }
    }
}

// ---------------- host side -------------------------------------------------
struct GemmArgs {
    const bf16 *Ah, *Al; long aGrp; int lda;
    const bf16 *WH, *WL; long wGrp;
    const float* Bias; long bGrp;
    float* Cf; long cfGrp; int ldcf;
    bf16 *OH, *OL; long oGrp; int ldo;
    int N, K, G;
};

template <int ACT, bool WF32, bool WB16>
static void rungemm(const GemmArgs& a) {
    dim3 grid((a.N + 127) / 128, BATCH / 128, a.G);
    gemm3<ACT, WF32, WB16><<<grid, 128, SMEM_BYTES>>>(
        a.Ah, a.Al, a.aGrp, a.lda, a.WH, a.WL, a.wGrp, a.Bias, a.bGrp, a.Cf,
        a.cfGrp, a.ldcf, a.OH, a.OL, a.oGrp, a.ldo, a.N, a.K);
}
template <int ACT, bool WF32, bool WB16>
static void rungemm_s(const GemmArgs& a) {
    dim3 grid((a.N + 63) / 64, BATCH / 64, a.G);
    gemm_s<ACT, WF32, WB16><<<grid, 128, SSMEM>>>(
        a.Ah, a.Al, a.aGrp, a.lda, a.WH, a.WL, a.wGrp, a.Bias, a.bGrp, a.Cf,
        a.cfGrp, a.ldcf, a.OH, a.OL, a.oGrp, a.ldo, a.N, a.K);
}

extern "C" void kernel_launch(void* const* d_in, const int* in_sizes, int n_in,
                              void* d_out, int out_size) {
    const float* in[31];
    for (int i = 0; i < 31; i++) in[i] = (const float*)d_in[i];
    const float* state = in[0];

    float* emb = (float*)d_out;                    // [4096, 85, 128]
    float* action = emb + (long)BATCH * 85 * 128;  // [4096, 32]

    bf16 *whi, *wlo, *h1h, *h1l, *h2h, *h2l, *th, *tl, *sh, *sl;
    cudaGetSymbolAddress((void**)&whi, g_whi);
    cudaGetSymbolAddress((void**)&wlo, g_wlo);
    cudaGetSymbolAddress((void**)&h1h, g_h1h);
    cudaGetSymbolAddress((void**)&h1l, g_h1l);
    cudaGetSymbolAddress((void**)&h2h, g_h2h);
    cudaGetSymbolAddress((void**)&h2l, g_h2l);
    cudaGetSymbolAddress((void**)&th, g_th);
    cudaGetSymbolAddress((void**)&tl, g_tl);
    cudaGetSymbolAddress((void**)&sh, g_sh);
    cudaGetSymbolAddress((void**)&sl, g_sl);

    cudaFuncSetAttribute(gemm3<1, false, true>,
                         cudaFuncAttributeMaxDynamicSharedMemorySize, SMEM_BYTES);
    cudaFuncSetAttribute(gemm3<0, true, true>,
                         cudaFuncAttributeMaxDynamicSharedMemorySize, SMEM_BYTES);
    cudaFuncSetAttribute(gemm_s<1, false, true>,
                         cudaFuncAttributeMaxDynamicSharedMemorySize, SSMEM);
    cudaFuncSetAttribute(gemm_s<0, true, true>,
                         cudaFuncAttributeMaxDynamicSharedMemorySize, SSMEM);
    cudaFuncSetAttribute(gemm_s<2, true, false>,
                         cudaFuncAttributeMaxDynamicSharedMemorySize, SSMEM);

    const int o_e1 = 0, o_eh = 2097152, o_eo = 3145728;
    const int o_01 = 4194304, o_0h = 8388608, o_0o = 12582912;
    const int o_11 = 13631488, o_1h = 14680064, o_1o = 15728640;
    const int o_21 = 15990784, o_2h = 16252928, o_2o = 16515072;
    const int o_h1 = 16580608, o_hh = 16596992, o_ho = 16613376;

    PrepJobs J;
    const int srcIdx[15] = {1, 3, 5, 7, 9, 11, 13, 15, 17, 19, 21, 23, 25, 27, 29};
    const int dofs[15] = {o_e1, o_eh, o_eo, o_01, o_0h, o_0o, o_11, o_1h,
                          o_1o, o_21, o_2h, o_2o, o_h1, o_hh, o_ho};
    const int Ks[15] = {256, 128, 128, 512, 512, 512, 512, 512,
                        512, 512, 512, 512, 128, 128, 128};
    const int Ns[15] = {128, 128, 128, 512, 512, 128, 512, 512,
                        128, 512, 512, 128, 128, 128, 32};
    const int Gs[15] = {64, 64, 64, 16, 16, 16, 4, 4, 4, 1, 1, 1, 1, 1, 1};
    int base = 0;
    for (int i = 0; i < 15; i++) {
        J.src[i] = in[srcIdx[i]];
        J.dstOff[i] = dofs[i];
        J.K[i] = Ks[i];
        J.N[i] = Ns[i];
        J.tileBase[i] = base;
        base += Gs[i] * (Ks[i] >> 5) * (Ns[i] >> 5);
    }
    J.tileBase[15] = base;
    prep_all<<<base, dim3(32, 8)>>>(J, whi, wlo);              // launch 1
    cvt_split<<<1024, 256>>>(state, sh, sl, BATCH * 256 / 4);  // launch 2

    const int D = 128, CD = 512;
    GemmArgs a;

    // encoders (G=64)                                          launches 3-5
    a = {sh, sl, 0L, 256, whi + o_e1, wlo + o_e1, 128L * 256, in[2], D,
         nullptr, 0L, 0, h1h, h1l, (long)BATCH * D, D, D, 256, 64};
    rungemm<1, false, true>(a);
    a = {h1h, h1l, (long)BATCH * D, D, whi + o_eh, wlo + o_eh, 128L * 128,
         in[4], D, nullptr, 0L, 0, h2h, h2l, (long)BATCH * D, D, D, 128, 64};
    rungemm<1, false, true>(a);
    a = {h2h, h2l, (long)BATCH * D, D, whi + o_eo, wlo + o_eo, 128L * 128,
         in[6], D, emb, (long)D, LDE, th, tl, (long)D, LDE, D, 128, 64};
    rungemm<0, true, true>(a);

    // agg0 (G=16)                                   launch 6 = ncu target
    a = {th, tl, 512L, LDE, whi + o_01, wlo + o_01, 512L * 512, in[8], CD,
         nullptr, 0L, 0, h1h, h1l, (long)BATCH * CD, CD, CD, 512, 16};
    rungemm<1, false, true>(a);
    a = {h1h, h1l, (long)BATCH * CD, CD, whi + o_0h, wlo + o_0h, 512L * 512,
         in[10], CD, nullptr, 0L, 0, h2h, h2l, (long)BATCH * CD, CD, CD, 512, 16};
    rungemm<1, false, true>(a);
    a = {h2h, h2l, (long)BATCH * CD, CD, whi + o_0o, wlo + o_0o, 128L * 512,
         in[12], D, emb + 64 * 128, (long)D, LDE, th + 64 * 128, tl + 64 * 128,
         (long)D, LDE, D, 512, 16};
    rungemm<0, true, true>(a);

    // agg1 (G=4)
    a = {th + 64 * 128, tl + 64 * 128, 512L, LDE, whi + o_11, wlo + o_11,
         512L * 512, in[14], CD, nullptr, 0L, 0, h1h, h1l, (long)BATCH * CD,
         CD, CD, 512, 4};
    rungemm<1, false, true>(a);
    a = {h1h, h1l, (long)BATCH * CD, CD, whi + o_1h, wlo + o_1h, 512L * 512,
         in[16], CD, nullptr, 0L, 0, h2h, h2l, (long)BATCH * CD, CD, CD, 512, 4};
    rungemm<1, false, true>(a);
    a = {h2h, h2l, (long)BATCH * CD, CD, whi + o_1o, wlo + o_1o, 128L * 512,
         in[18], D, emb + 80 * 128, (long)D, LDE, th + 80 * 128, tl + 80 * 128,
         (long)D, LDE, D, 512, 4};
    rungemm_s<0, true, true>(a);

    // agg2 (G=1) — SMALL kernel
    a = {th + 80 * 128, tl + 80 * 128, 0L, LDE, whi + o_21, wlo + o_21, 0L,
         in[20], 0L, nullptr, 0L, 0, h1h, h1l, 0L, CD, CD, 512, 1};
    rungemm_s<1, false, true>(a);
    a = {h1h, h1l, 0L, CD, whi + o_2h, wlo + o_2h, 0L, in[22], 0L, nullptr, 0L,
         0, h2h, h2l, 0L, CD, CD, 512, 1};
    rungemm_s<1, false, true>(a);
    a = {h2h, h2l, 0L, CD, whi + o_2o, wlo + o_2o, 0L, in[24], 0L,
         emb + 84 * 128, 0L, LDE, th + 84 * 128, tl + 84 * 128, 0L, LDE, D,
         512, 1};
    rungemm_s<0, true, true>(a);

    // head (G=1) — SMALL kernel
    a = {th + 84 * 128, tl + 84 * 128, 0L, LDE, whi + o_h1, wlo + o_h1, 0L,
         in[26], 0L, nullptr, 0L, 0, h1h, h1l, 0L, D, D, 128, 1};
    rungemm_s<1, false, true>(a);
    a = {h1h, h1l, 0L, D, whi + o_hh, wlo + o_hh, 0L, in[28], 0L, nullptr, 0L,
         0, h2h, h2l, 0L, D, D, 128, 1};
    rungemm_s<1, false, true>(a);
    a = {h2h, h2l, 0L, D, whi + o_ho, wlo + o_ho, 0L, in[30], 0L, action, 0L,
         32, nullptr, nullptr, 0L, 0, 32, 128, 1};
    rungemm_s<2, true, false>(a);
}

// round 13
// speedup vs baseline: 1.0513x; 1.0513x over previous
#include <cuda_runtime.h>
#include <cuda_bf16.h>
#include <cstdint>
#include <math.h>

// ===========================================================================
// Actor_15324443312913 — HMMA bf16 hi/lo-split grouped GEMM, round 13.
//  * big kernel reverted to R11 shape (256 thr, 64x32 warp tile, 124 regs)
//  * NEW: enc_fused — state->L1->Lh->Lo in ONE kernel (h via smem)
//  * NEW: tail_fused — agg2o->head1->headh->action in ONE kernel
//  * 17 launches -> 12
// ===========================================================================

#define BATCH 4096
#define LDE   (85 * 128)

typedef __nv_bfloat16 bf16;

#define WT_TOTAL 16617472
__device__ bf16 g_whi[WT_TOTAL];
__device__ bf16 g_wlo[WT_TOTAL];
__device__ bf16 g_h1h[33554432], g_h1l[33554432];
__device__ bf16 g_h2h[33554432], g_h2l[33554432];
__device__ bf16 g_th[44564480], g_tl[44564480];
__device__ bf16 g_sh[1048576], g_sl[1048576];

// ---------------- helpers ---------------------------------------------------
__device__ __forceinline__ uint32_t smem_u32(const void* p) {
    uint32_t a;
    asm("{ .reg .u64 t; cvta.to.shared.u64 t, %1; cvt.u32.u64 %0, t; }"
        : "=r"(a) : "l"(p));
    return a;
}
__device__ __forceinline__ void ldsm4(uint32_t* r, uint32_t addr) {
    asm volatile("ldmatrix.sync.aligned.m8n8.x4.shared.b16 {%0,%1,%2,%3}, [%4];"
                 : "=r"(r[0]), "=r"(r[1]), "=r"(r[2]), "=r"(r[3]) : "r"(addr));
}
__device__ __forceinline__ void mma_bf16(float* c, const uint32_t* a,
                                         const uint32_t* b) {
    asm volatile(
        "mma.sync.aligned.m16n8k16.row.col.f32.bf16.bf16.f32 "
        "{%0,%1,%2,%3},{%4,%5,%6,%7},{%8,%9},{%0,%1,%2,%3};"
        : "+f"(c[0]), "+f"(c[1]), "+f"(c[2]), "+f"(c[3])
        : "r"(a[0]), "r"(a[1]), "r"(a[2]), "r"(a[3]), "r"(b[0]), "r"(b[1]));
}
__device__ __forceinline__ void cpa16(uint32_t dst, const void* src, bool p) {
    int sz = p ? 16 : 0;
    asm volatile("cp.async.cg.shared.global [%0], [%1], 16, %2;"
                 :: "r"(dst), "l"(src), "r"(sz));
}
#define CP_COMMIT() asm volatile("cp.async.commit_group;" ::: "memory")
#define CP_WAIT0()  asm volatile("cp.async.wait_group 0;" ::: "memory")

__device__ __forceinline__ void split2(float x, float y, uint32_t& h2,
                                       uint32_t& l2) {
    __nv_bfloat162 h, l;
    h.x = __float2bfloat16(x); h.y = __float2bfloat16(y);
    l.x = __float2bfloat16(x - __bfloat162float(h.x));
    l.y = __float2bfloat16(y - __bfloat162float(h.y));
    h2 = *(uint32_t*)&h;
    l2 = *(uint32_t*)&l;
}

// ---------------- fused weight prep ----------------------------------------
struct PrepJobs {
    const float* src[15];
    int dstOff[15];
    int K[15], N[15];
    int tileBase[16];
};

__global__ void prep_all(PrepJobs J, bf16* __restrict__ hi,
                         bf16* __restrict__ lo) {
    __shared__ float t[32][33];
    const int bz = blockIdx.x;
    int j = 0;
#pragma unroll
    for (int i = 1; i < 15; i++)
        if (bz >= J.tileBase[i]) j = i;
    const int rem = bz - J.tileBase[j];
    const int K = J.K[j], N = J.N[j];
    const int ntx = N >> 5;
    const int perG = ntx * (K >> 5);
    const int g = rem / perG;
    const int tt = rem % perG;
    const int k0 = (tt / ntx) << 5, n0 = (tt % ntx) << 5;

    const long grp = (long)K * N;
    const float* ing = J.src[j] + (long)g * grp;
    bf16* hig = hi + J.dstOff[j] + (long)g * grp;
    bf16* log_ = lo + J.dstOff[j] + (long)g * grp;
    const int tx = threadIdx.x, ty = threadIdx.y;
#pragma unroll
    for (int i = 0; i < 32; i += 8)
        t[ty + i][tx] = ing[(long)(k0 + ty + i) * N + n0 + tx];
    __syncthreads();
#pragma unroll
    for (int i = 0; i < 32; i += 8) {
        float v = t[tx][ty + i];
        bf16 h = __float2bfloat16(v);
        float r = v - __bfloat162float(h);
        long o = (long)(n0 + ty + i) * K + k0 + tx;
        hig[o] = h;
        log_[o] = __float2bfloat16(r);
    }
}

__global__ void cvt_split(const float* __restrict__ in, bf16* __restrict__ hi,
                          bf16* __restrict__ lo, int n4) {
    int i = blockIdx.x * blockDim.x + threadIdx.x;
    if (i < n4) {
        float4 t = ((const float4*)in)[i];
        uint32_t h01, l01, h23, l23;
        split2(t.x, t.y, h01, l01);
        split2(t.z, t.w, h23, l23);
        ((uint2*)hi)[i] = make_uint2(h01, h23);
        ((uint2*)lo)[i] = make_uint2(l01, l23);
    }
}

// ---------------- epilogue helper (global) ----------------------------------
template <int ACT, bool WF32, bool WB16>
__device__ __forceinline__ void epi_store(const float* c, const float* sBias,
                                          int lc, int r0, float* Cfg, int ldcf,
                                          bf16* OHg, bf16* OLg, int ldo,
                                          int col) {
    float b0 = sBias[lc], b1 = sBias[lc + 1];
    float2 v0 = make_float2(c[0] + b0, c[1] + b1);
    float2 v1 = make_float2(c[2] + b0, c[3] + b1);
    if (ACT == 1) {
        v0.x = fmaxf(v0.x, 0.f); v0.y = fmaxf(v0.y, 0.f);
        v1.x = fmaxf(v1.x, 0.f); v1.y = fmaxf(v1.y, 0.f);
    }
    if (ACT == 2) {
        v0.x = tanhf(v0.x); v0.y = tanhf(v0.y);
        v1.x = tanhf(v1.x); v1.y = tanhf(v1.y);
    }
    if (WF32) {
        *(float2*)(Cfg + (long)r0 * ldcf + col) = v0;
        *(float2*)(Cfg + (long)(r0 + 8) * ldcf + col) = v1;
    }
    if (WB16) {
        uint32_t h2, l2;
        split2(v0.x, v0.y, h2, l2);
        *(uint32_t*)(OHg + (long)r0 * ldo + col) = h2;
        *(uint32_t*)(OLg + (long)r0 * ldo + col) = l2;
        split2(v1.x, v1.y, h2, l2);
        *(uint32_t*)(OHg + (long)(r0 + 8) * ldo + col) = h2;
        *(uint32_t*)(OLg + (long)(r0 + 8) * ldo + col) = l2;
    }
}

// ---------------- BIG GEMM (R11): 128x128 tile, 256 thr ---------------------
#define STAGE_BYTES 40960
#define SMEM_BYTES  (2 * STAGE_BYTES + 512)

__device__ __forceinline__ void stage_tiles(
    uint32_t sb, const bf16* Ahg, const bf16* Alg, int lda, const bf16* WHg,
    const bf16* WLg, int K, int k0, int n0, int N, int tid) {
#pragma unroll
    for (int i = 0; i < 2; i++) {
        int v = tid + (i << 8);
        int r = v >> 2, q = v & 3;
        uint32_t d = (uint32_t)(r * 80 + (q << 4));
        long ao = (long)r * lda + k0 + (q << 3);
        cpa16(sb + d, Ahg + ao, true);
        cpa16(sb + 10240 + d, Alg + ao, true);
        bool bp = (n0 + r) < N;
        long bo = bp ? ((long)r * K + k0 + (q << 3)) : 0;
        cpa16(sb + 20480 + d, WHg + bo, bp);
        cpa16(sb + 30720 + d, WLg + bo, bp);
    }
}

template <int ACT, bool WF32, bool WB16>
__global__ __launch_bounds__(256, 2)
void gemm2(const bf16* __restrict__ Ah, const bf16* __restrict__ Al, long aGrp,
           int lda, const bf16* __restrict__ WH, const bf16* __restrict__ WL,
           long wGrp, const float* __restrict__ Bias, long bGrp,
           float* __restrict__ Cf, long cfGrp, int ldcf,
           bf16* __restrict__ OH, bf16* __restrict__ OL, long oGrp, int ldo,
           int N, int K) {
    extern __shared__ char smem[];
    const uint32_t sbs = smem_u32(smem);
    float* sBias = (float*)(smem + 2 * STAGE_BYTES);

    const int tid = threadIdx.x, w = tid >> 5, L = tid & 31;
    const int wr = w >> 2, wc = w & 3;
    const int g = blockIdx.z;
    const int m0 = blockIdx.y * 128, n0 = blockIdx.x * 128;

    const bf16* Ahg = Ah + (long)g * aGrp + (long)m0 * lda;
    const bf16* Alg = Al + (long)g * aGrp + (long)m0 * lda;
    const bf16* WHg = WH + (long)g * wGrp + (long)n0 * K;
    const bf16* WLg = WL + (long)g * wGrp + (long)n0 * K;

    if (tid < 128) {
        int c = n0 + tid;
        sBias[tid] = (c < N) ? Bias[(long)g * bGrp + c] : 0.f;
    }

    float acc[64];
#pragma unroll
    for (int i = 0; i < 64; i++) acc[i] = 0.f;

    const uint32_t a_off =
        (uint32_t)((wr * 64 + (L & 7) + ((L >> 3) & 1) * 8) * 80 +
                   ((L >> 4) & 1) * 16);
    const uint32_t b_off =
        (uint32_t)((wc * 32 + (L & 7) + ((L >> 4) & 1) * 8) * 80 +
                   ((L >> 3) & 1) * 16);

    const int nch = K >> 5;
    stage_tiles(sbs, Ahg, Alg, lda, WHg, WLg, K, 0, n0, N, tid);
    CP_COMMIT();

    for (int ch = 0; ch < nch; ch++) {
        CP_WAIT0();
        __syncthreads();
        if (ch + 1 < nch)
            stage_tiles(sbs + ((ch + 1) & 1) * STAGE_BYTES, Ahg, Alg, lda, WHg,
                        WLg, K, (ch + 1) << 5, n0, N, tid);
        CP_COMMIT();

        const uint32_t ab = sbs + (ch & 1) * STAGE_BYTES;
        const uint32_t bb = ab + 20480;
#pragma unroll
        for (int s = 0; s < 2; s++) {
            uint32_t ah[16], al[16], bh[8], bl[8];
#pragma unroll
            for (int p = 0; p < 2; p++) {
                uint32_t bd = b_off + p * 1280 + s * 32;
                ldsm4(&bh[p * 4], bb + bd);
                ldsm4(&bl[p * 4], bb + 10240 + bd);
            }
#pragma unroll
            for (int mt = 0; mt < 4; mt++) {
                uint32_t ad = a_off + mt * 1280 + s * 32;
                ldsm4(&ah[mt * 4], ab + ad);
                ldsm4(&al[mt * 4], ab + 10240 + ad);
            }
#pragma unroll
            for (int p = 0; p < 2; p++) {
#pragma unroll
                for (int mt = 0; mt < 4; mt++)
#pragma unroll
                    for (int t = 0; t < 2; t++)
                        mma_bf16(&acc[(mt * 4 + p * 2 + t) * 4], &ah[mt * 4],
                                 &bh[p * 4 + t * 2]);
#pragma unroll
                for (int mt = 0; mt < 4; mt++)
#pragma unroll
                    for (int t = 0; t < 2; t++)
                        mma_bf16(&acc[(mt * 4 + p * 2 + t) * 4], &ah[mt * 4],
                                 &bl[p * 4 + t * 2]);
#pragma unroll
                for (int mt = 0; mt < 4; mt++)
#pragma unroll
                    for (int t = 0; t < 2; t++)
                        mma_bf16(&acc[(mt * 4 + p * 2 + t) * 4], &al[mt * 4],
                                 &bh[p * 4 + t * 2]);
            }
        }
    }

    const int quad = L >> 2, ql = L & 3;
    float* Cfg = Cf + (long)g * cfGrp;
    bf16* OHg = OH + (long)g * oGrp;
    bf16* OLg = OL + (long)g * oGrp;
#pragma unroll
    for (int mt = 0; mt < 4; mt++) {
        int r0 = m0 + wr * 64 + mt * 16 + quad;
#pragma unroll
        for (int nt = 0; nt < 4; nt++) {
            int lc = wc * 32 + nt * 8 + (ql << 1);
            int col = n0 + lc;
            if (col < N)
                epi_store<ACT, WF32, WB16>(&acc[(mt * 4 + nt) * 4], sBias, lc,
                                           r0, Cfg, ldcf, OHg, OLg, ldo, col);
        }
    }
}

// ---------------- SMALL GEMM: 64x64 tile, 128 thr ---------------------------
#define SSTAGE 20480
#define SSMEM  (2 * SSTAGE + 512)

__device__ __forceinline__ void stage_small(
    uint32_t sb, const bf16* Ahg, const bf16* Alg, int lda, const bf16* WHg,
    const bf16* WLg, int K, int k0, int n0, int N, int tid) {
#pragma unroll
    for (int i = 0; i < 2; i++) {
        int v = tid + (i << 7);
        int r = v >> 2, q = v & 3;
        uint32_t d = (uint32_t)(r * 80 + (q << 4));
        long ao = (long)r * lda + k0 + (q << 3);
        cpa16(sb + d, Ahg + ao, true);
        cpa16(sb + 5120 + d, Alg + ao, true);
        bool bp = (n0 + r) < N;
        long bo = bp ? ((long)r * K + k0 + (q << 3)) : 0;
        cpa16(sb + 10240 + d, WHg + bo, bp);
        cpa16(sb + 15360 + d, WLg + bo, bp);
    }
}

template <int ACT, bool WF32, bool WB16>
__global__ __launch_bounds__(128, 4)
void gemm_s(const bf16* __restrict__ Ah, const bf16* __restrict__ Al,
            long aGrp, int lda, const bf16* __restrict__ WH,
            const bf16* __restrict__ WL, long wGrp,
            const float* __restrict__ Bias, long bGrp,
            float* __restrict__ Cf, long cfGrp, int ldcf,
            bf16* __restrict__ OH, bf16* __restrict__ OL, long oGrp, int ldo,
            int N, int K) {
    extern __shared__ char smem[];
    const uint32_t sbs = smem_u32(smem);
    float* sBias = (float*)(smem + 2 * SSTAGE);

    const int tid = threadIdx.x, w = tid >> 5, L = tid & 31;
    const int wr = w >> 1, wc = w & 1;
    const int g = blockIdx.z;
    const int m0 = blockIdx.y * 64, n0 = blockIdx.x * 64;

    const bf16* Ahg = Ah + (long)g * aGrp + (long)m0 * lda;
    const bf16* Alg = Al + (long)g * aGrp + (long)m0 * lda;
    const bf16* WHg = WH + (long)g * wGrp + (long)n0 * K;
    const bf16* WLg = WL + (long)g * wGrp + (long)n0 * K;

    if (tid < 64) {
        int c = n0 + tid;
        sBias[tid] = (c < N) ? Bias[(long)g * bGrp + c] : 0.f;
    }

    float acc[32];
#pragma unroll
    for (int i = 0; i < 32; i++) acc[i] = 0.f;

    const uint32_t a_off =
        (uint32_t)((wr * 32 + (L & 7) + ((L >> 3) & 1) * 8) * 80 +
                   ((L >> 4) & 1) * 16);
    const uint32_t b_off =
        (uint32_t)((wc * 32 + (L & 7) + ((L >> 4) & 1) * 8) * 80 +
                   ((L >> 3) & 1) * 16);

    const int nch = K >> 5;
    stage_small(sbs, Ahg, Alg, lda, WHg, WLg, K, 0, n0, N, tid);
    CP_COMMIT();

    for (int ch = 0; ch < nch; ch++) {
        CP_WAIT0();
        __syncthreads();
        if (ch + 1 < nch)
            stage_small(sbs + ((ch + 1) & 1) * SSTAGE, Ahg, Alg, lda, WHg, WLg,
                        K, (ch + 1) << 5, n0, N, tid);
        CP_COMMIT();

        const uint32_t ab = sbs + (ch & 1) * SSTAGE;
        const uint32_t bb = ab + 10240;
#pragma unroll
        for (int s = 0; s < 2; s++) {
            uint32_t ah[8], al[8], bh[8], bl[8];
#pragma unroll
            for (int p = 0; p < 2; p++) {
                uint32_t bd = b_off + p * 1280 + s * 32;
                ldsm4(&bh[p * 4], bb + bd);
                ldsm4(&bl[p * 4], bb + 5120 + bd);
            }
#pragma unroll
            for (int mt = 0; mt < 2; mt++) {
                uint32_t ad = a_off + mt * 1280 + s * 32;
                ldsm4(&ah[mt * 4], ab + ad);
                ldsm4(&al[mt * 4], ab + 5120 + ad);
            }
#pragma unroll
            for (int p = 0; p < 2; p++) {
#pragma unroll
                for (int mt = 0; mt < 2; mt++)
#pragma unroll
                    for (int t = 0; t < 2; t++)
                        mma_bf16(&acc[(mt * 4 + p * 2 + t) * 4], &ah[mt * 4],
                                 &bh[p * 4 + t * 2]);
#pragma unroll
                for (int mt = 0; mt < 2; mt++)
#pragma unroll
                    for (int t = 0; t < 2; t++)
                        mma_bf16(&acc[(mt * 4 + p * 2 + t) * 4], &ah[mt * 4],
                                 &bl[p * 4 + t * 2]);
#pragma unroll
                for (int mt = 0; mt < 2; mt++)
#pragma unroll
                    for (int t = 0; t < 2; t++)
                        mma_bf16(&acc[(mt * 4 + p * 2 + t) * 4], &al[mt * 4],
                                 &bh[p * 4 + t * 2]);
            }
        }
    }

    const int quad = L >> 2, ql = L & 3;
    float* Cfg = Cf + (long)g * cfGrp;
    bf16* OHg = OH + (long)g * oGrp;
    bf16* OLg = OL + (long)g * oGrp;
#pragma unroll
    for (int mt = 0; mt < 2; mt++) {
        int r0 = m0 + wr * 32 + mt * 16 + quad;
#pragma unroll
        for (int nt = 0; nt < 4; nt++) {
            int lc = wc * 32 + nt * 8 + (ql << 1);
            int col = n0 + lc;
            if (col < N)
                epi_store<ACT, WF32, WB16>(&acc[(mt * 4 + nt) * 4], sBias, lc,
                                           r0, Cfg, ldcf, OHg, OLg, ldo, col);
        }
    }
}

// ============================================================================
// FUSED CHAIN KERNELS (N == 128 chains, h passed via smem)
// smem map: [0,40960)       : B double-stage (hi at +0, lo at +10240)
//           [40960,110592)  : phase-1 A stages, later hA (hi 40960, lo 75776)
//           [110592,+2048)  : biases (4 x 128 floats)
// ============================================================================
#define FS_B0   0
#define FS_A0   40960
#define FS_HH   40960
#define FS_HL   75776
#define FS_BIAS 110592
#define FSMEM   112640

// stage A(128x32)+B(128x32) hi/lo from global
__device__ __forceinline__ void fstage_AB(uint32_t sbs, int st,
                                          const bf16* Ah, const bf16* Al,
                                          int lda, const bf16* WH,
                                          const bf16* WL, int ldw, int k0,
                                          int tid) {
    uint32_t aB = sbs + FS_A0 + st * 20480;
    uint32_t bB = sbs + st * 20480;
#pragma unroll
    for (int i = 0; i < 2; i++) {
        int v = tid + (i << 8);
        int r = v >> 2, q = v & 3;
        uint32_t d = (uint32_t)(r * 80 + (q << 4));
        long ao = (long)r * lda + k0 + (q << 3);
        cpa16(aB + d, Ah + ao, true);
        cpa16(aB + 10240 + d, Al + ao, true);
        long bo = (long)r * ldw + k0 + (q << 3);
        cpa16(bB + d, WH + bo, true);
        cpa16(bB + 10240 + d, WL + bo, true);
    }
}

// stage only B(128x32) hi/lo; rows >= Nvalid zero-filled
__device__ __forceinline__ void fstage_B(uint32_t sbs, int st, const bf16* WH,
                                         const bf16* WL, int ldw, int k0,
                                         int Nvalid, int tid) {
    uint32_t bB = sbs + st * 20480;
#pragma unroll
    for (int i = 0; i < 2; i++) {
        int v = tid + (i << 8);
        int r = v >> 2, q = v & 3;
        uint32_t d = (uint32_t)(r * 80 + (q << 4));
        bool bp = r < Nvalid;
        long bo = bp ? ((long)r * ldw + k0 + (q << 3)) : 0;
        cpa16(bB + d, WH + bo, bp);
        cpa16(bB + 10240 + d, WL + bo, bp);
    }
}

// one K-chunk of MMAs; A from (ahB,alB)+a_off pattern, B from stage st
__device__ __forceinline__ void fcompute(uint32_t ahB, uint32_t alB,
                                         int a_stride_mt, uint32_t a_off,
                                         uint32_t bB, uint32_t b_off,
                                         float* acc) {
#pragma unroll
    for (int s = 0; s < 2; s++) {
        uint32_t ah[16], al[16], bh[8], bl[8];
#pragma unroll
        for (int p = 0; p < 2; p++) {
            uint32_t bd = b_off + p * 1280 + s * 32;
            ldsm4(&bh[p * 4], bB + bd);
            ldsm4(&bl[p * 4], bB + 10240 + bd);
        }
#pragma unroll
        for (int mt = 0; mt < 4; mt++) {
            uint32_t ad = a_off + mt * a_stride_mt + s * 32;
            ldsm4(&ah[mt * 4], ahB + ad);
            ldsm4(&al[mt * 4], alB + ad);
        }
#pragma unroll
        for (int p = 0; p < 2; p++) {
#pragma unroll
            for (int mt = 0; mt < 4; mt++)
#pragma unroll
                for (int t = 0; t < 2; t++)
                    mma_bf16(&acc[(mt * 4 + p * 2 + t) * 4], &ah[mt * 4],
                             &bh[p * 4 + t * 2]);
#pragma unroll
            for (int mt = 0; mt < 4; mt++)
#pragma unroll
                for (int t = 0; t < 2; t++)
                    mma_bf16(&acc[(mt * 4 + p * 2 + t) * 4], &ah[mt * 4],
                             &bl[p * 4 + t * 2]);
#pragma unroll
            for (int mt = 0; mt < 4; mt++)
#pragma unroll
                for (int t = 0; t < 2; t++)
                    mma_bf16(&acc[(mt * 4 + p * 2 + t) * 4], &al[mt * 4],
                             &bh[p * 4 + t * 2]);
        }
    }
}

// phase with A in GLOBAL (staged): nch chunks of 32
__device__ __forceinline__ void fphase_globalA(
    uint32_t sbs, const bf16* Ah, const bf16* Al, int lda, const bf16* WH,
    const bf16* WL, int ldw, int K, int tid, uint32_t a_off, uint32_t b_off,
    float* acc) {
    const int nch = K >> 5;
    fstage_AB(sbs, 0, Ah, Al, lda, WH, WL, ldw, 0, tid);
    CP_COMMIT();
    for (int ch = 0; ch < nch; ch++) {
        CP_WAIT0();
        __syncthreads();
        if (ch + 1 < nch)
            fstage_AB(sbs, (ch + 1) & 1, Ah, Al, lda, WH, WL, ldw,
                      (ch + 1) << 5, tid);
        CP_COMMIT();
        uint32_t aB = sbs + FS_A0 + (ch & 1) * 20480;
        fcompute(aB, aB + 10240, 1280, a_off, sbs + (ch & 1) * 20480, b_off,
                 acc);
    }
    __syncthreads();  // A/B stages + all compute done
}

// phase with A in smem hA (stride 272), K=128 fixed (4 chunks)
__device__ __forceinline__ void fphase_smemA(uint32_t sbs, const bf16* WH,
                                             const bf16* WL, int ldw,
                                             int Nvalid, int tid,
                                             uint32_t ha_off, uint32_t b_off,
                                             float* acc) {
    fstage_B(sbs, 0, WH, WL, ldw, 0, Nvalid, tid);
    CP_COMMIT();
    for (int ch = 0; ch < 4; ch++) {
        CP_WAIT0();
        __syncthreads();
        if (ch + 1 < 4)
            fstage_B(sbs, (ch + 1) & 1, WH, WL, ldw, (ch + 1) << 5, Nvalid,
                     tid);
        CP_COMMIT();
        fcompute(sbs + FS_HH, sbs + FS_HL, 16 * 272, ha_off + ch * 64,
                 sbs + (ch & 1) * 20480, b_off, acc);
    }
    __syncthreads();
}

// epilogue -> hA in smem (bias + optional relu + split)
__device__ __forceinline__ void fepi_smem(char* smem, const float* acc,
                                          const float* sB, int wr, int wc,
                                          int quad, int ql, bool relu) {
#pragma unroll
    for (int mt = 0; mt < 4; mt++) {
        int rl = wr * 64 + mt * 16 + quad;
#pragma unroll
        for (int nt = 0; nt < 4; nt++) {
            int lc = wc * 32 + nt * 8 + (ql << 1);
            const float* c = &acc[(mt * 4 + nt) * 4];
            float b0 = sB[lc], b1 = sB[lc + 1];
            float v0x = c[0] + b0, v0y = c[1] + b1;
            float v1x = c[2] + b0, v1y = c[3] + b1;
            if (relu) {
                v0x = fmaxf(v0x, 0.f); v0y = fmaxf(v0y, 0.f);
                v1x = fmaxf(v1x, 0.f); v1y = fmaxf(v1y, 0.f);
            }
            uint32_t h2, l2;
            split2(v0x, v0y, h2, l2);
            *(uint32_t*)(smem + FS_HH + rl * 272 + lc * 2) = h2;
            *(uint32_t*)(smem + FS_HL + rl * 272 + lc * 2) = l2;
            split2(v1x, v1y, h2, l2);
            *(uint32_t*)(smem + FS_HH + (rl + 8) * 272 + lc * 2) = h2;
            *(uint32_t*)(smem + FS_HL + (rl + 8) * 272 + lc * 2) = l2;
        }
    }
}

// ---------------- enc_fused: state -> L1 -> Lh -> Lo ------------------------
__global__ __launch_bounds__(256, 2)
void enc_fused(const bf16* __restrict__ sh, const bf16* __restrict__ sl,
               const bf16* __restrict__ w1h, const bf16* __restrict__ w1l,
               const bf16* __restrict__ whh, const bf16* __restrict__ whl,
               const bf16* __restrict__ woh, const bf16* __restrict__ wol,
               const float* __restrict__ b1, const float* __restrict__ bh_,
               const float* __restrict__ bo_, float* __restrict__ emb,
               bf16* __restrict__ th, bf16* __restrict__ tl) {
    extern __shared__ char smem[];
    const uint32_t sbs = smem_u32(smem);
    const int tid = threadIdx.x, w = tid >> 5, L = tid & 31;
    const int wr = w >> 2, wc = w & 3, quad = L >> 2, ql = L & 3;
    const int g = blockIdx.z, m0 = blockIdx.y * 128;

    const bf16* Ah = sh + (long)m0 * 256;
    const bf16* Al = sl + (long)m0 * 256;
    const bf16* W1H = w1h + (long)g * (128 * 256);
    const bf16* W1L = w1l + (long)g * (128 * 256);
    const bf16* WHH = whh + (long)g * (128 * 128);
    const bf16* WHL = whl + (long)g * (128 * 128);
    const bf16* WOH = woh + (long)g * (128 * 128);
    const bf16* WOL = wol + (long)g * (128 * 128);

    float* sB = (float*)(smem + FS_BIAS);
    if (tid < 128) {
        sB[tid] = b1[g * 128 + tid];
        sB[128 + tid] = bh_[g * 128 + tid];
        sB[256 + tid] = bo_[g * 128 + tid];
    }

    const uint32_t a_off =
        (uint32_t)((wr * 64 + (L & 7) + ((L >> 3) & 1) * 8) * 80 +
                   ((L >> 4) & 1) * 16);
    const uint32_t b_off =
        (uint32_t)((wc * 32 + (L & 7) + ((L >> 4) & 1) * 8) * 80 +
                   ((L >> 3) & 1) * 16);
    const uint32_t ha_off =
        (uint32_t)((wr * 64 + (L & 7) + ((L >> 3) & 1) * 8) * 272 +
                   ((L >> 4) & 1) * 16);

    float acc[64];

    // phase 1: K=256
#pragma unroll
    for (int i = 0; i < 64; i++) acc[i] = 0.f;
    fphase_globalA(sbs, Ah, Al, 256, W1H, W1L, 256, 256, tid, a_off, b_off,
                   acc);
    fepi_smem(smem, acc, sB, wr, wc, quad, ql, true);
    __syncthreads();

    // phase 2: K=128, A from hA
#pragma unroll
    for (int i = 0; i < 64; i++) acc[i] = 0.f;
    fphase_smemA(sbs, WHH, WHL, 128, 128, tid, ha_off, b_off, acc);
    fepi_smem(smem, acc, sB + 128, wr, wc, quad, ql, true);
    __syncthreads();

    // phase 3: K=128, output layer (no act), write emb fp32 + tree bf16
#pragma unroll
    for (int i = 0; i < 64; i++) acc[i] = 0.f;
    fphase_smemA(sbs, WOH, WOL, 128, 128, tid, ha_off, b_off, acc);

    float* Cfg = emb + g * 128;
    bf16* OHg = th + g * 128;
    bf16* OLg = tl + g * 128;
#pragma unroll
    for (int mt = 0; mt < 4; mt++) {
        int r0 = m0 + wr * 64 + mt * 16 + quad;
#pragma unroll
        for (int nt = 0; nt < 4; nt++) {
            int lc = wc * 32 + nt * 8 + (ql << 1);
            epi_store<0, true, true>(&acc[(mt * 4 + nt) * 4], sB + 256, lc, r0,
                                     Cfg, LDE, OHg, OLg, LDE, lc);
        }
    }
}

// ---------------- tail_fused: agg2o -> head1 -> headh -> action -------------
__global__ __launch_bounds__(256)
void tail_fused(const bf16* __restrict__ a2h, const bf16* __restrict__ a2l,
                const bf16* __restrict__ w2oh, const bf16* __restrict__ w2ol,
                const bf16* __restrict__ hw1h, const bf16* __restrict__ hw1l,
                const bf16* __restrict__ hwhh, const bf16* __restrict__ hwhl,
                const bf16* __restrict__ hwoh, const bf16* __restrict__ hwol,
                const float* __restrict__ b2o, const float* __restrict__ hb1,
                const float* __restrict__ hbh, const float* __restrict__ hbo,
                float* __restrict__ emb84, bf16* __restrict__ th84,
                bf16* __restrict__ tl84, float* __restrict__ action) {
    extern __shared__ char smem[];
    const uint32_t sbs = smem_u32(smem);
    const int tid = threadIdx.x, w = tid >> 5, L = tid & 31;
    const int wr = w >> 2, wc = w & 3, quad = L >> 2, ql = L & 3;
    const int m0 = blockIdx.y * 128;

    float* sB = (float*)(smem + FS_BIAS);
    if (tid < 128) {
        sB[tid] = b2o[tid];
        sB[128 + tid] = hb1[tid];
        sB[256 + tid] = hbh[tid];
        sB[384 + tid] = (tid < 32) ? hbo[tid] : 0.f;
    }

    const uint32_t a_off =
        (uint32_t)((wr * 64 + (L & 7) + ((L >> 3) & 1) * 8) * 80 +
                   ((L >> 4) & 1) * 16);
    const uint32_t b_off =
        (uint32_t)((wc * 32 + (L & 7) + ((L >> 4) & 1) * 8) * 80 +
                   ((L >> 3) & 1) * 16);
    const uint32_t ha_off =
        (uint32_t)((wr * 64 + (L & 7) + ((L >> 3) & 1) * 8) * 272 +
                   ((L >> 4) & 1) * 16);

    float acc[64];

    // phase 0: agg2 output layer, K=512, A = agg2 hidden2 (ld 512)
#pragma unroll
    for (int i = 0; i < 64; i++) acc[i] = 0.f;
    fphase_globalA(sbs, a2h + (long)m0 * 512, a2l + (long)m0 * 512, 512, w2oh,
                   w2ol, 512, 512, tid, a_off, b_off, acc);
    // epilogue: emb node 84 (fp32) + hA (split, no act)
    {
#pragma unroll
        for (int mt = 0; mt < 4; mt++) {
            int r0 = m0 + wr * 64 + mt * 16 + quad;
#pragma unroll
            for (int nt = 0; nt < 4; nt++) {
                int lc = wc * 32 + nt * 8 + (ql << 1);
                epi_store<0, true, false>(&acc[(mt * 4 + nt) * 4], sB, lc, r0,
                                          emb84, LDE, nullptr, nullptr, 0, lc);
            }
        }
        fepi_smem(smem, acc, sB, wr, wc, quad, ql, false);
        // also mirror to tree (node 84) for completeness
#pragma unroll
        for (int mt = 0; mt < 4; mt++) {
            int r0 = m0 + wr * 64 + mt * 16 + quad;
#pragma unroll
            for (int nt = 0; nt < 4; nt++) {
                int lc = wc * 32 + nt * 8 + (ql << 1);
                const float* c = &acc[(mt * 4 + nt) * 4];
                float b0 = sB[lc], b1 = sB[lc + 1];
                uint32_t h2, l2;
                split2(c[0] + b0, c[1] + b1, h2, l2);
                *(uint32_t*)(th84 + (long)r0 * LDE + lc) = h2;
                *(uint32_t*)(tl84 + (long)r0 * LDE + lc) = l2;
                split2(c[2] + b0, c[3] + b1, h2, l2);
                *(uint32_t*)(th84 + (long)(r0 + 8) * LDE + lc) = h2;
                *(uint32_t*)(tl84 + (long)(r0 + 8) * LDE + lc) = l2;
            }
        }
    }
    __syncthreads();

    // phase 1: head L1 (K=128, relu)
#pragma unroll
    for (int i = 0; i < 64; i++) acc[i] = 0.f;
    fphase_smemA(sbs, hw1h, hw1l, 128, 128, tid, ha_off, b_off, acc);
    fepi_smem(smem, acc, sB + 128, wr, wc, quad, ql, true);
    __syncthreads();

    // phase 2: head Lh (K=128, relu)
#pragma unroll
    for (int i = 0; i < 64; i++) acc[i] = 0.f;
    fphase_smemA(sbs, hwhh, hwhl, 128, 128, tid, ha_off, b_off, acc);
    fepi_smem(smem, acc, sB + 256, wr, wc, quad, ql, true);
    __syncthreads();

    // phase 3: head out (K=128, N=32, tanh)
#pragma unroll
    for (int i = 0; i < 64; i++) acc[i] = 0.f;
    fphase_smemA(sbs, hwoh, hwol, 128, 32, tid, ha_off, b_off, acc);
    if (wc == 0) {
#pragma unroll
        for (int mt = 0; mt < 4; mt++) {
            int r0 = m0 + wr * 64 + mt * 16 + quad;
#pragma unroll
            for (int nt = 0; nt < 4; nt++) {
                int lc = nt * 8 + (ql << 1);
                const float* c = &acc[(mt * 4 + nt) * 4];
                float b0 = sB[384 + lc], b1 = sB[384 + lc + 1];
                float2 v0 = make_float2(tanhf(c[0] + b0), tanhf(c[1] + b1));
                float2 v1 = make_float2(tanhf(c[2] + b0), tanhf(c[3] + b1));
                *(float2*)(action + (long)r0 * 32 + lc) = v0;
                *(float2*)(action + (long)(r0 + 8) * 32 + lc) = v1;
            }
        }
    }
}

// ---------------- host side -------------------------------------------------
struct GemmArgs {
    const bf16 *Ah, *Al; long aGrp; int lda;
    const bf16 *WH, *WL; long wGrp;
    const float* Bias; long bGrp;
    float* Cf; long cfGrp; int ldcf;
    bf16 *OH, *OL; long oGrp; int ldo;
    int N, K, G;
};

template <int ACT, bool WF32, bool WB16>
static void rungemm(const GemmArgs& a) {
    dim3 grid((a.N + 127) / 128, BATCH / 128, a.G);
    gemm2<ACT, WF32, WB16><<<grid, 256, SMEM_BYTES>>>(
        a.Ah, a.Al, a.aGrp, a.lda, a.WH, a.WL, a.wGrp, a.Bias, a.bGrp, a.Cf,
        a.cfGrp, a.ldcf, a.OH, a.OL, a.oGrp, a.ldo, a.N, a.K);
}
template <int ACT, bool WF32, bool WB16>
static void rungemm_s(const GemmArgs& a) {
    dim3 grid((a.N + 63) / 64, BATCH / 64, a.G);
    gemm_s<ACT, WF32, WB16><<<grid, 128, SSMEM>>>(
        a.Ah, a.Al, a.aGrp, a.lda, a.WH, a.WL, a.wGrp, a.Bias, a.bGrp, a.Cf,
        a.cfGrp, a.ldcf, a.OH, a.OL, a.oGrp, a.ldo, a.N, a.K);
}

extern "C" void kernel_launch(void* const* d_in, const int* in_sizes, int n_in,
                              void* d_out, int out_size) {
    const float* in[31];
    for (int i = 0; i < 31; i++) in[i] = (const float*)d_in[i];
    const float* state = in[0];

    float* emb = (float*)d_out;                    // [4096, 85, 128]
    float* action = emb + (long)BATCH * 85 * 128;  // [4096, 32]

    bf16 *whi, *wlo, *h1h, *h1l, *h2h, *h2l, *th, *tl, *sh, *sl;
    cudaGetSymbolAddress((void**)&whi, g_whi);
    cudaGetSymbolAddress((void**)&wlo, g_wlo);
    cudaGetSymbolAddress((void**)&h1h, g_h1h);
    cudaGetSymbolAddress((void**)&h1l, g_h1l);
    cudaGetSymbolAddress((void**)&h2h, g_h2h);
    cudaGetSymbolAddress((void**)&h2l, g_h2l);
    cudaGetSymbolAddress((void**)&th, g_th);
    cudaGetSymbolAddress((void**)&tl, g_tl);
    cudaGetSymbolAddress((void**)&sh, g_sh);
    cudaGetSymbolAddress((void**)&sl, g_sl);

    cudaFuncSetAttribute(gemm2<1, false, true>,
                         cudaFuncAttributeMaxDynamicSharedMemorySize, SMEM_BYTES);
    cudaFuncSetAttribute(gemm2<0, true, true>,
                         cudaFuncAttributeMaxDynamicSharedMemorySize, SMEM_BYTES);
    cudaFuncSetAttribute(gemm_s<1, false, true>,
                         cudaFuncAttributeMaxDynamicSharedMemorySize, SSMEM);
    cudaFuncSetAttribute(gemm_s<0, true, true>,
                         cudaFuncAttributeMaxDynamicSharedMemorySize, SSMEM);
    cudaFuncSetAttribute(enc_fused,
                         cudaFuncAttributeMaxDynamicSharedMemorySize, FSMEM);
    cudaFuncSetAttribute(tail_fused,
                         cudaFuncAttributeMaxDynamicSharedMemorySize, FSMEM);

    const int o_e1 = 0, o_eh = 2097152, o_eo = 3145728;
    const int o_01 = 4194304, o_0h = 8388608, o_0o = 12582912;
    const int o_11 = 13631488, o_1h = 14680064, o_1o = 15728640;
    const int o_21 = 15990784, o_2h = 16252928, o_2o = 16515072;
    const int o_h1 = 16580608, o_hh = 16596992, o_ho = 16613376;

    PrepJobs J;
    const int srcIdx[15] = {1, 3, 5, 7, 9, 11, 13, 15, 17, 19, 21, 23, 25, 27, 29};
    const int dofs[15] = {o_e1, o_eh, o_eo, o_01, o_0h, o_0o, o_11, o_1h,
                          o_1o, o_21, o_2h, o_2o, o_h1, o_hh, o_ho};
    const int Ks[15] = {256, 128, 128, 512, 512, 512, 512, 512,
                        512, 512, 512, 512, 128, 128, 128};
    const int Ns[15] = {128, 128, 128, 512, 512, 128, 512, 512,
                        128, 512, 512, 128, 128, 128, 32};
    const int Gs[15] = {64, 64, 64, 16, 16, 16, 4, 4, 4, 1, 1, 1, 1, 1, 1};
    int base = 0;
    for (int i = 0; i < 15; i++) {
        J.src[i] = in[srcIdx[i]];
        J.dstOff[i] = dofs[i];
        J.K[i] = Ks[i];
        J.N[i] = Ns[i];
        J.tileBase[i] = base;
        base += Gs[i] * (Ks[i] >> 5) * (Ns[i] >> 5);
    }
    J.tileBase[15] = base;
    prep_all<<<base, dim3(32, 8)>>>(J, whi, wlo);              // launch 1
    cvt_split<<<1024, 256>>>(state, sh, sl, BATCH * 256 / 4);  // launch 2

    // encoders fused                                           launch 3
    enc_fused<<<dim3(1, 32, 64), 256, FSMEM>>>(
        sh, sl, whi + o_e1, wlo + o_e1, whi + o_eh, wlo + o_eh, whi + o_eo,
        wlo + o_eo, in[2], in[4], in[6], emb, th, tl);

    const int D = 128, CD = 512;
    GemmArgs a;

    // agg0 (G=16)                           launches 4,5,6 (6 = ncu target)
    a = {th, tl, 512L, LDE, whi + o_01, wlo + o_01, 512L * 512, in[8], CD,
         nullptr, 0L, 0, h1h, h1l, (long)BATCH * CD, CD, CD, 512, 16};
    rungemm<1, false, true>(a);
    a = {h1h, h1l, (long)BATCH * CD, CD, whi + o_0h, wlo + o_0h, 512L * 512,
         in[10], CD, nullptr, 0L, 0, h2h, h2l, (long)BATCH * CD, CD, CD, 512, 16};
    rungemm<1, false, true>(a);
    a = {h2h, h2l, (long)BATCH * CD, CD, whi + o_0o, wlo + o_0o, 128L * 512,
         in[12], D, emb + 64 * 128, (long)D, LDE, th + 64 * 128, tl + 64 * 128,
         (long)D, LDE, D, 512, 16};
    rungemm<0, true, true>(a);

    // agg1 (G=4)
    a = {th + 64 * 128, tl + 64 * 128, 512L, LDE, whi + o_11, wlo + o_11,
         512L * 512, in[14], CD, nullptr, 0L, 0, h1h, h1l, (long)BATCH * CD,
         CD, CD, 512, 4};
    rungemm<1, false, true>(a);
    a = {h1h, h1l, (long)BATCH * CD, CD, whi + o_1h, wlo + o_1h, 512L * 512,
         in[16], CD, nullptr, 0L, 0, h2h, h2l, (long)BATCH * CD, CD, CD, 512, 4};
    rungemm<1, false, true>(a);
    a = {h2h, h2l, (long)BATCH * CD, CD, whi + o_1o, wlo + o_1o, 128L * 512,
         in[18], D, emb + 80 * 128, (long)D, LDE, th + 80 * 128, tl + 80 * 128,
         (long)D, LDE, D, 512, 4};
    rungemm_s<0, true, true>(a);

    // agg2 L1 / Lh (G=1) — SMALL kernel
    a = {th + 80 * 128, tl + 80 * 128, 0L, LDE, whi + o_21, wlo + o_21, 0L,
         in[20], 0L, nullptr, 0L, 0, h1h, h1l, 0L, CD, CD, 512, 1};
    rungemm_s<1, false, true>(a);
    a = {h1h, h1l, 0L, CD, whi + o_2h, wlo + o_2h, 0L, in[22], 0L, nullptr, 0L,
         0, h2h, h2l, 0L, CD, CD, 512, 1};
    rungemm_s<1, false, true>(a);

    // agg2o + head chain fused                                 launch 12
    tail_fused<<<dim3(1, 32, 1), 256, FSMEM>>>(
        h2h, h2l, whi + o_2o, wlo + o_2o, whi + o_h1, wlo + o_h1, whi + o_hh,
        wlo + o_hh, whi + o_ho, wlo + o_ho, in[24], in[26], in[28], in[30],
        emb + 84 * 128, th + 84 * 128, tl + 84 * 128, action);
}